// round 2
// baseline (speedup 1.0000x reference)
#include <cuda_runtime.h>
#include <math.h>

// Problem constants
#define TOK   8192      // B*L
#define HIDN  2048
#define PW    8192      // QKV (6144) + gate (2048)
#define LSEQ  2048
#define ATT_SMEM ((64*132*2 + 64*68)*4)

// Scratch (allocation-free rule: device globals)
__device__ float g_proj[(size_t)TOK * PW];   // 256 MB
__device__ float g_att [(size_t)TOK * HIDN]; //  64 MB

// ---------------------------------------------------------------------------
// Tiled fp32 GEMM: C[M,N] = A[M,K] @ B[K,N], all row-major.
// 128x128 block tile, BK=16, 256 threads, 8x8 per thread. M,N%128==0, K%16==0.
// ---------------------------------------------------------------------------
__global__ __launch_bounds__(256) void sgemm128(const float* __restrict__ A,
                                                const float* __restrict__ B,
                                                float* __restrict__ C,
                                                int M, int N, int K)
{
    __shared__ float As[16][132];   // A transposed: As[k][m]
    __shared__ float Bs[16][128];
    const int tid = threadIdx.x;
    const int tx = tid & 15, ty = tid >> 4;
    const int bm = blockIdx.y << 7, bn = blockIdx.x << 7;

    float acc[8][8];
    #pragma unroll
    for (int i = 0; i < 8; i++)
        #pragma unroll
        for (int j = 0; j < 8; j++) acc[i][j] = 0.f;

    for (int k0 = 0; k0 < K; k0 += 16) {
        #pragma unroll
        for (int t = tid; t < 512; t += 256) {      // A tile: 128x16
            int r = t >> 2, c4 = (t & 3) << 2;
            float4 v = *(const float4*)&A[(size_t)(bm + r) * K + k0 + c4];
            As[c4 + 0][r] = v.x; As[c4 + 1][r] = v.y;
            As[c4 + 2][r] = v.z; As[c4 + 3][r] = v.w;
        }
        #pragma unroll
        for (int t = tid; t < 512; t += 256) {      // B tile: 16x128
            int r = t >> 5, c4 = (t & 31) << 2;
            *(float4*)&Bs[r][c4] = *(const float4*)&B[(size_t)(k0 + r) * N + bn + c4];
        }
        __syncthreads();
        #pragma unroll
        for (int kk = 0; kk < 16; kk++) {
            float a[8], bb[8];
            *(float4*)&a[0]  = *(const float4*)&As[kk][ty * 8];
            *(float4*)&a[4]  = *(const float4*)&As[kk][ty * 8 + 4];
            *(float4*)&bb[0] = *(const float4*)&Bs[kk][tx * 8];
            *(float4*)&bb[4] = *(const float4*)&Bs[kk][tx * 8 + 4];
            #pragma unroll
            for (int i = 0; i < 8; i++)
                #pragma unroll
                for (int j = 0; j < 8; j++)
                    acc[i][j] += a[i] * bb[j];
        }
        __syncthreads();
    }
    #pragma unroll
    for (int i = 0; i < 8; i++) {
        size_t row = (size_t)(bm + ty * 8 + i) * N + bn + tx * 8;
        *(float4*)&C[row]     = make_float4(acc[i][0], acc[i][1], acc[i][2], acc[i][3]);
        *(float4*)&C[row + 4] = make_float4(acc[i][4], acc[i][5], acc[i][6], acc[i][7]);
    }
}

// ---------------------------------------------------------------------------
// Per-token post-processing, in place on g_proj:
//   heads 0..15 (Q) and 16..31 (K): per-head RMSNorm (DH=128) then RoPE.
//   gate columns [6144,8192): sigmoid.
// One block per token, 128 threads. RoPE angles computed once (fp64) per token.
// ---------------------------------------------------------------------------
__global__ __launch_bounds__(128) void postproc(float* __restrict__ proj)
{
    __shared__ float cosv[64], sinv[64], xbuf[128], red[4];
    const int row = blockIdx.x;           // token index b*L + l
    const int l   = row & (LSEQ - 1);     // position within sequence
    const int tid = threadIdx.x;

    if (tid < 64) {
        double f   = pow(10000.0, -(double)tid / 64.0);  // theta^{-2i/DH}
        double ang = (double)l * f;
        double s, c;
        sincos(ang, &s, &c);
        cosv[tid] = (float)c;
        sinv[tid] = (float)s;
    }
    __syncthreads();

    const size_t base0 = (size_t)row * PW;
    for (int hh = 0; hh < 32; hh++) {                 // 16 q heads + 16 k heads
        const size_t base = base0 + hh * 128;
        float x = proj[base + tid];
        float v = x * x;
        #pragma unroll
        for (int o = 16; o; o >>= 1) v += __shfl_xor_sync(0xffffffffu, v, o);
        if ((tid & 31) == 0) red[tid >> 5] = v;
        __syncthreads();
        float total = red[0] + red[1] + red[2] + red[3];
        float scale = 1.0f / sqrtf(total * 0.0078125f + 1e-5f);
        xbuf[tid] = x * scale;
        __syncthreads();
        if (tid < 64) {
            float x1 = xbuf[tid], x2 = xbuf[tid + 64];
            float c = cosv[tid], s = sinv[tid];
            proj[base + tid]      = x1 * c - x2 * s;
            proj[base + tid + 64] = x1 * s + x2 * c;
        }
        __syncthreads();
    }
    // gate sigmoid
    for (int it = 0; it < 16; it++) {
        size_t idx = base0 + 6144 + it * 128 + tid;
        float g = proj[idx];
        proj[idx] = 1.0f / (1.0f + expf(-g));
    }
}

// ---------------------------------------------------------------------------
// fp32 causal flash attention (BM=BN=64), gate fused into epilogue.
// Q/K/V read from g_proj (token-major, per-head 128-col slices).
// grid = (32 q-blocks, 64 batch*head), 256 threads, 85 KB dynamic smem.
// ---------------------------------------------------------------------------
__global__ __launch_bounds__(256) void attn_kernel(const float* __restrict__ proj,
                                                   float* __restrict__ att)
{
    extern __shared__ float sm[];
    float* Qs  = sm;                 // [64][132]
    float* KVs = sm + 64 * 132;      // [64][132] (K then reused for V)
    float* Ps  = sm + 2 * 64 * 132;  // [64][68]

    const int tid = threadIdx.x;
    const int tx = tid & 15, ty = tid >> 4;
    const int ty4 = ty << 2, tx4 = tx << 2, tx8 = tx << 3;
    const int qb  = (int)gridDim.x - 1 - (int)blockIdx.x;  // heavy blocks first
    const int b   = blockIdx.y >> 4, h = blockIdx.y & 15;
    const int q0  = qb << 6;
    const size_t tokbase = (size_t)b * LSEQ;
    const int coff = h * 128;
    const float qs = 0.08838834764831845f;   // 1/sqrt(128)

    // Load Q tile (prescaled)
    for (int t = tid; t < 2048; t += 256) {
        int r = t >> 5, c4 = (t & 31) << 2;
        float4 v = *(const float4*)&proj[(tokbase + q0 + r) * PW + coff + c4];
        v.x *= qs; v.y *= qs; v.z *= qs; v.w *= qs;
        *(float4*)&Qs[r * 132 + c4] = v;
    }

    float m[4], lsum[4], o[4][8];
    #pragma unroll
    for (int i = 0; i < 4; i++) {
        m[i] = -INFINITY; lsum[i] = 0.f;
        #pragma unroll
        for (int j = 0; j < 8; j++) o[i][j] = 0.f;
    }

    for (int kt = 0; kt <= qb; kt++) {
        const int k0 = kt << 6;
        // load K tile
        for (int t = tid; t < 2048; t += 256) {
            int r = t >> 5, c4 = (t & 31) << 2;
            *(float4*)&KVs[r * 132 + c4] =
                *(const float4*)&proj[(tokbase + k0 + r) * PW + 2048 + coff + c4];
        }
        __syncthreads();

        // S = Q K^T (4x4 per thread)
        float acc[4][4];
        #pragma unroll
        for (int i = 0; i < 4; i++)
            #pragma unroll
            for (int j = 0; j < 4; j++) acc[i][j] = 0.f;
        for (int kk = 0; kk < 128; kk += 4) {
            float4 qv[4], kv[4];
            #pragma unroll
            for (int i = 0; i < 4; i++) qv[i] = *(const float4*)&Qs[(ty4 + i) * 132 + kk];
            #pragma unroll
            for (int j = 0; j < 4; j++) kv[j] = *(const float4*)&KVs[(tx4 + j) * 132 + kk];
            #pragma unroll
            for (int i = 0; i < 4; i++)
                #pragma unroll
                for (int j = 0; j < 4; j++)
                    acc[i][j] += qv[i].x * kv[j].x + qv[i].y * kv[j].y
                               + qv[i].z * kv[j].z + qv[i].w * kv[j].w;
        }

        // online softmax
        const bool diag = (kt == qb);
        #pragma unroll
        for (int i = 0; i < 4; i++) {
            int qg = q0 + ty4 + i;
            if (diag) {
                #pragma unroll
                for (int j = 0; j < 4; j++)
                    if (k0 + tx4 + j > qg) acc[i][j] = -INFINITY;
            }
            float mloc = fmaxf(fmaxf(acc[i][0], acc[i][1]), fmaxf(acc[i][2], acc[i][3]));
            #pragma unroll
            for (int off = 8; off; off >>= 1)
                mloc = fmaxf(mloc, __shfl_xor_sync(0xffffffffu, mloc, off));
            float mnew  = fmaxf(m[i], mloc);
            float alpha = expf(m[i] - mnew);
            float rs = 0.f;
            #pragma unroll
            for (int j = 0; j < 4; j++) {
                float p = expf(acc[i][j] - mnew);
                Ps[(ty4 + i) * 68 + tx4 + j] = p;
                rs += p;
            }
            #pragma unroll
            for (int off = 8; off; off >>= 1)
                rs += __shfl_xor_sync(0xffffffffu, rs, off);
            lsum[i] = lsum[i] * alpha + rs;
            m[i] = mnew;
            #pragma unroll
            for (int j = 0; j < 8; j++) o[i][j] *= alpha;
        }
        __syncthreads();

        // load V tile into same buffer
        for (int t = tid; t < 2048; t += 256) {
            int r = t >> 5, c4 = (t & 31) << 2;
            *(float4*)&KVs[r * 132 + c4] =
                *(const float4*)&proj[(tokbase + k0 + r) * PW + 4096 + coff + c4];
        }
        __syncthreads();

        // O += P @ V  (4 rows x 8 cols per thread)
        for (int kk = 0; kk < 64; kk++) {
            float4 v0 = *(const float4*)&KVs[kk * 132 + tx8];
            float4 v1 = *(const float4*)&KVs[kk * 132 + tx8 + 4];
            #pragma unroll
            for (int i = 0; i < 4; i++) {
                float p = Ps[(ty4 + i) * 68 + kk];
                o[i][0] += p * v0.x; o[i][1] += p * v0.y;
                o[i][2] += p * v0.z; o[i][3] += p * v0.w;
                o[i][4] += p * v1.x; o[i][5] += p * v1.y;
                o[i][6] += p * v1.z; o[i][7] += p * v1.w;
            }
        }
        __syncthreads();
    }

    // epilogue: normalize, apply sigmoid gate, store
    #pragma unroll
    for (int i = 0; i < 4; i++) {
        int qg = q0 + ty4 + i;
        size_t prow = (tokbase + qg) * PW;
        size_t arow = (tokbase + qg) * HIDN;
        float inv = 1.0f / lsum[i];
        #pragma unroll
        for (int j = 0; j < 8; j++) {
            int d = tx8 + j;
            float g = proj[prow + 6144 + coff + d];
            att[arow + coff + d] = o[i][j] * inv * g;
        }
    }
}

// ---------------------------------------------------------------------------
extern "C" void kernel_launch(void* const* d_in, const int* in_sizes, int n_in,
                              void* d_out, int out_size)
{
    const float* hs    = (const float*)d_in[0];   // (4,2048,2048)
    const float* wqkvg = (const float*)d_in[1];   // (2048,8192)
    const float* wout  = (const float*)d_in[2];   // (2048,2048)
    float* out = (float*)d_out;

    float *proj, *att;
    cudaGetSymbolAddress((void**)&proj, g_proj);
    cudaGetSymbolAddress((void**)&att,  g_att);

    // 1) QKVG projection
    sgemm128<<<dim3(PW / 128, TOK / 128), 256>>>(hs, wqkvg, proj, TOK, PW, HIDN);
    // 2) RMSNorm + RoPE (q,k) + sigmoid gate, in place
    postproc<<<TOK, 128>>>(proj);
    // 3) causal flash attention with fused gate
    cudaFuncSetAttribute(attn_kernel, cudaFuncAttributeMaxDynamicSharedMemorySize, ATT_SMEM);
    attn_kernel<<<dim3(32, 64), 256, ATT_SMEM>>>(proj, att);
    // 4) output projection
    sgemm128<<<dim3(HIDN / 128, TOK / 128), 256>>>(att, wout, out, TOK, HIDN, HIDN);
}

// round 5
// speedup vs baseline: 2.8786x; 2.8786x over previous
#include <cuda_runtime.h>
#include <cuda_bf16.h>
#include <cstdint>
#include <math.h>

// Problem constants
#define TOK   8192      // B*L
#define HIDN  2048
#define PW    8192      // QKV (6144) + gate (2048)
#define LSEQ  2048
#define ATT_SMEM ((64*132*2 + 64*68)*4)

// ---------------------------------------------------------------------------
// Global scratch (allocation-free rule: device globals)
// ---------------------------------------------------------------------------
__device__ float          g_proj [(size_t)TOK * PW];    // 256 MB fp32
__device__ __nv_bfloat16  g_hs_hi[(size_t)TOK * HIDN];
__device__ __nv_bfloat16  g_hs_lo[(size_t)TOK * HIDN];
__device__ __nv_bfloat16  g_wq_hi[(size_t)PW  * HIDN];  // W_qkvg^T  [N][K]
__device__ __nv_bfloat16  g_wq_lo[(size_t)PW  * HIDN];
__device__ __nv_bfloat16  g_wo_hi[(size_t)HIDN* HIDN];  // W_out^T   [N][K]
__device__ __nv_bfloat16  g_wo_lo[(size_t)HIDN* HIDN];
__device__ __nv_bfloat16  g_at_hi[(size_t)TOK * HIDN];
__device__ __nv_bfloat16  g_at_lo[(size_t)TOK * HIDN];

// ---------------------------------------------------------------------------
// Helpers
// ---------------------------------------------------------------------------
__device__ __forceinline__ uint32_t smem_to_u32(const void* smem_ptr) {
    uint32_t addr;
    asm("{ .reg .u64 tmp; cvta.to.shared.u64 tmp, %1; cvt.u32.u64 %0, tmp; }"
        : "=r"(addr) : "l"(smem_ptr));
    return addr;
}

#define SMEM_SWIZZLE_128B(byte_offset) \
    ((byte_offset) ^ ((((uint32_t)(byte_offset)) >> 3) & 0x70u))

#define CP_ASYNC_16(smem_u32, gptr) \
    asm volatile("cp.async.cg.shared.global [%0], [%1], 16;" \
                 :: "r"(smem_u32), "l"(gptr) : "memory")
#define CP_ASYNC_COMMIT() asm volatile("cp.async.commit_group;" ::: "memory")
#define CP_ASYNC_WAIT_1() asm volatile("cp.async.wait_group 1;" ::: "memory")
#define CP_ASYNC_WAIT_0() asm volatile("cp.async.wait_group 0;" ::: "memory")

#define LDSM_X4(r0, r1, r2, r3, addr) \
    asm volatile("ldmatrix.sync.aligned.m8n8.x4.shared.b16 {%0,%1,%2,%3}, [%4];" \
                 : "=r"(r0), "=r"(r1), "=r"(r2), "=r"(r3) : "r"(addr))

#define MMA_16816(c, a, b) \
    asm volatile("mma.sync.aligned.m16n8k16.row.col.f32.bf16.bf16.f32 " \
                 "{%0,%1,%2,%3}, {%4,%5,%6,%7}, {%8,%9}, {%0,%1,%2,%3};" \
                 : "+f"((c)[0]), "+f"((c)[1]), "+f"((c)[2]), "+f"((c)[3]) \
                 : "r"((a)[0]), "r"((a)[1]), "r"((a)[2]), "r"((a)[3]), \
                   "r"((b)[0]), "r"((b)[1]))

// ---------------------------------------------------------------------------
// elementwise fp32 -> bf16 hi/lo split
// ---------------------------------------------------------------------------
__global__ __launch_bounds__(256) void split_kernel(const float* __restrict__ x,
                                                    __nv_bfloat16* __restrict__ hi,
                                                    __nv_bfloat16* __restrict__ lo, int n4)
{
    int i = blockIdx.x * 256 + threadIdx.x;
    if (i >= n4) return;
    float4 v = ((const float4*)x)[i];
    float vv[4];
    vv[0] = v.x; vv[1] = v.y; vv[2] = v.z; vv[3] = v.w;
    __nv_bfloat16 hbuf[4], lbuf[4];
    #pragma unroll
    for (int j = 0; j < 4; j++) {
        __nv_bfloat16 h = __float2bfloat16(vv[j]);
        hbuf[j] = h;
        lbuf[j] = __float2bfloat16(vv[j] - __bfloat162float(h));
    }
    *(uint2*)&hi[(size_t)i * 4] = *(const uint2*)hbuf;
    *(uint2*)&lo[(size_t)i * 4] = *(const uint2*)lbuf;
}

// ---------------------------------------------------------------------------
// W [K][N] fp32  ->  Wt_hi/Wt_lo [N][K] bf16 (transpose + split)
// ---------------------------------------------------------------------------
__global__ __launch_bounds__(256) void tsplit_kernel(const float* __restrict__ W,
                                                     __nv_bfloat16* __restrict__ hi,
                                                     __nv_bfloat16* __restrict__ lo,
                                                     int K, int N)
{
    __shared__ float t[32][33];
    const int bn = blockIdx.x * 32;
    const int bk = blockIdx.y * 32;
    const int x = threadIdx.x & 31;
    const int y4 = (threadIdx.x >> 5) * 4;
    #pragma unroll
    for (int r = 0; r < 4; r++)
        t[y4 + r][x] = W[(size_t)(bk + y4 + r) * N + bn + x];
    __syncthreads();
    #pragma unroll
    for (int r = 0; r < 4; r++) {
        float v = t[x][y4 + r];
        __nv_bfloat16 h = __float2bfloat16(v);
        size_t o = (size_t)(bn + y4 + r) * K + bk + x;
        hi[o] = h;
        lo[o] = __float2bfloat16(v - __bfloat162float(h));
    }
}

// ---------------------------------------------------------------------------
// HMMA bf16x3 GEMM: C[M,N] = A[M,K] @ Bt[N,K]^T (fp32-equivalent precision).
// CTA 128x128, BK=64 (SW128 rows of 128B), 8 warps (64x32 each),
// cp.async double buffer, m16n8k16 bf16 mma with fp32 accumulate.
// ---------------------------------------------------------------------------
#define GSM_TILE  16384           // one 128x64 bf16 tile
#define GSM_BUF   (4 * GSM_TILE)  // Ah, Al, Bh, Bl
#define GSM_TOTAL (2 * GSM_BUF)   // double buffered = 128 KB

__global__ __launch_bounds__(256) void gemm_bf16x3(
    const __nv_bfloat16* __restrict__ Ahi, const __nv_bfloat16* __restrict__ Alo,
    const __nv_bfloat16* __restrict__ Bhi, const __nv_bfloat16* __restrict__ Blo,
    float* __restrict__ C, int M, int N, int K)
{
    extern __shared__ char smc[];
    const uint32_t sb = smem_to_u32(smc);
    const int tid  = threadIdx.x;
    const int wid  = tid >> 5;
    const int lane = tid & 31;
    const int wm   = wid & 1;          // warp row (2 x 64)
    const int wn   = wid >> 1;         // warp col (4 x 32)
    const int bm   = blockIdx.y << 7;
    const int bn   = blockIdx.x << 7;

    // loader mapping: 16B per thread per (tile,row-pass)
    const int r0  = tid >> 3;          // 0..31
    const int c16 = tid & 7;           // 16B column in the 128B row

    const __nv_bfloat16* srcs[4];
    srcs[0] = Ahi + (size_t)bm * K;
    srcs[1] = Alo + (size_t)bm * K;
    srcs[2] = Bhi + (size_t)bn * K;
    srcs[3] = Blo + (size_t)bn * K;

    const int nc = K >> 6;             // K chunks of 64

    // ---- issue cp.async loads for chunk c into buffer buf ----
    auto issue_chunk = [&](int c, int buf) {
        const int k0 = c << 6;
        const uint32_t bufb = sb + buf * GSM_BUF;
        #pragma unroll
        for (int t = 0; t < 4; t++) {
            const __nv_bfloat16* s = srcs[t] + k0;
            #pragma unroll
            for (int rr = 0; rr < 4; rr++) {
                const int r = r0 + rr * 32;
                const uint32_t so = bufb + t * GSM_TILE +
                    SMEM_SWIZZLE_128B((uint32_t)(r * 128 + c16 * 16));
                CP_ASYNC_16(so, s + (size_t)r * K + c16 * 8);
            }
        }
    };

    float acc[4][4][4];
    #pragma unroll
    for (int mi = 0; mi < 4; mi++)
        #pragma unroll
        for (int ni = 0; ni < 4; ni++)
            #pragma unroll
            for (int j = 0; j < 4; j++) acc[mi][ni][j] = 0.f;

    // ldmatrix lane -> (row, k-half) mapping
    const int lr   = lane & 7;
    const int a_row = lr + ((lane >> 3) & 1) * 8;    // + m0
    const int a_kb  = ((lane >> 4) & 1) * 16;        // bytes, + ks*32
    const int b_row = lr + ((lane >> 4) & 1) * 8;    // + n0
    const int b_kb  = ((lane >> 3) & 1) * 16;

    issue_chunk(0, 0);
    CP_ASYNC_COMMIT();

    for (int c = 0; c < nc; c++) {
        const int buf = c & 1;
        if (c + 1 < nc) {
            issue_chunk(c + 1, buf ^ 1);
            CP_ASYNC_COMMIT();
            CP_ASYNC_WAIT_1();
        } else {
            CP_ASYNC_WAIT_0();
        }
        __syncthreads();

        const uint32_t Ab = sb + buf * GSM_BUF;          // Ah (Al at +GSM_TILE)
        const uint32_t Bb = Ab + 2 * GSM_TILE;           // Bh (Bl at +GSM_TILE)

        #pragma unroll
        for (int ks = 0; ks < 4; ks++) {
            uint32_t ah[4][4], al[4][4], bh[4][2], bl[4][2];
            #pragma unroll
            for (int mi = 0; mi < 4; mi++) {
                const uint32_t off = SMEM_SWIZZLE_128B(
                    (uint32_t)((wm * 64 + mi * 16 + a_row) * 128 + ks * 32 + a_kb));
                LDSM_X4(ah[mi][0], ah[mi][1], ah[mi][2], ah[mi][3], Ab + off);
                LDSM_X4(al[mi][0], al[mi][1], al[mi][2], al[mi][3], Ab + GSM_TILE + off);
            }
            #pragma unroll
            for (int nb = 0; nb < 2; nb++) {
                const uint32_t off = SMEM_SWIZZLE_128B(
                    (uint32_t)((wn * 32 + nb * 16 + b_row) * 128 + ks * 32 + b_kb));
                uint32_t q0, q1, q2, q3;
                LDSM_X4(q0, q1, q2, q3, Bb + off);
                bh[nb * 2][0] = q0; bh[nb * 2][1] = q1;
                bh[nb * 2 + 1][0] = q2; bh[nb * 2 + 1][1] = q3;
                LDSM_X4(q0, q1, q2, q3, Bb + GSM_TILE + off);
                bl[nb * 2][0] = q0; bl[nb * 2][1] = q1;
                bl[nb * 2 + 1][0] = q2; bl[nb * 2 + 1][1] = q3;
            }
            #pragma unroll
            for (int mi = 0; mi < 4; mi++)
                #pragma unroll
                for (int ni = 0; ni < 4; ni++) {
                    MMA_16816(acc[mi][ni], ah[mi], bh[ni]);
                    MMA_16816(acc[mi][ni], ah[mi], bl[ni]);
                    MMA_16816(acc[mi][ni], al[mi], bh[ni]);
                }
        }
        __syncthreads();
    }

    // epilogue: c-frag -> C (row g / g+8, cols 2t, 2t+1)
    const int g = lane >> 2, t2 = (lane & 3) * 2;
    #pragma unroll
    for (int mi = 0; mi < 4; mi++) {
        const int row0 = bm + wm * 64 + mi * 16 + g;
        #pragma unroll
        for (int ni = 0; ni < 4; ni++) {
            const int col = bn + wn * 32 + ni * 8 + t2;
            float2 v0; v0.x = acc[mi][ni][0]; v0.y = acc[mi][ni][1];
            float2 v1; v1.x = acc[mi][ni][2]; v1.y = acc[mi][ni][3];
            *(float2*)&C[(size_t)row0 * N + col]       = v0;
            *(float2*)&C[(size_t)(row0 + 8) * N + col] = v1;
        }
    }
}

// ---------------------------------------------------------------------------
// Per-token post-processing: RMSNorm + RoPE on q/k heads, sigmoid on gate.
// ---------------------------------------------------------------------------
__global__ __launch_bounds__(128) void postproc(float* __restrict__ proj)
{
    __shared__ float cosv[64], sinv[64], xbuf[128], red[4];
    const int row = blockIdx.x;
    const int l   = row & (LSEQ - 1);
    const int tid = threadIdx.x;

    if (tid < 64) {
        double f   = pow(10000.0, -(double)tid / 64.0);
        double ang = (double)l * f;
        double s, c;
        sincos(ang, &s, &c);
        cosv[tid] = (float)c;
        sinv[tid] = (float)s;
    }
    __syncthreads();

    const size_t base0 = (size_t)row * PW;
    for (int hh = 0; hh < 32; hh++) {
        const size_t base = base0 + hh * 128;
        float x = proj[base + tid];
        float v = x * x;
        #pragma unroll
        for (int o = 16; o; o >>= 1) v += __shfl_xor_sync(0xffffffffu, v, o);
        if ((tid & 31) == 0) red[tid >> 5] = v;
        __syncthreads();
        float total = red[0] + red[1] + red[2] + red[3];
        float scale = 1.0f / sqrtf(total * 0.0078125f + 1e-5f);
        xbuf[tid] = x * scale;
        __syncthreads();
        if (tid < 64) {
            float x1 = xbuf[tid], x2 = xbuf[tid + 64];
            float c = cosv[tid], s = sinv[tid];
            proj[base + tid]      = x1 * c - x2 * s;
            proj[base + tid + 64] = x1 * s + x2 * c;
        }
        __syncthreads();
    }
    for (int it = 0; it < 16; it++) {
        size_t idx = base0 + 6144 + it * 128 + tid;
        float g = proj[idx];
        proj[idx] = 1.0f / (1.0f + expf(-g));
    }
}

// ---------------------------------------------------------------------------
// fp32 causal flash attention, gate fused; epilogue writes bf16 hi/lo split.
// ---------------------------------------------------------------------------
__global__ __launch_bounds__(256) void attn_kernel(const float* __restrict__ proj,
                                                   __nv_bfloat16* __restrict__ att_hi,
                                                   __nv_bfloat16* __restrict__ att_lo)
{
    extern __shared__ float sm[];
    float* Qs  = sm;
    float* KVs = sm + 64 * 132;
    float* Ps  = sm + 2 * 64 * 132;

    const int tid = threadIdx.x;
    const int tx = tid & 15, ty = tid >> 4;
    const int ty4 = ty << 2, tx4 = tx << 2, tx8 = tx << 3;
    const int qb  = (int)gridDim.x - 1 - (int)blockIdx.x;
    const int b   = blockIdx.y >> 4, h = blockIdx.y & 15;
    const int q0  = qb << 6;
    const size_t tokbase = (size_t)b * LSEQ;
    const int coff = h * 128;
    const float qs = 0.08838834764831845f;

    for (int t = tid; t < 2048; t += 256) {
        int r = t >> 5, c4 = (t & 31) << 2;
        float4 v = *(const float4*)&proj[(tokbase + q0 + r) * PW + coff + c4];
        v.x *= qs; v.y *= qs; v.z *= qs; v.w *= qs;
        *(float4*)&Qs[r * 132 + c4] = v;
    }

    float m[4], lsum[4], o[4][8];
    #pragma unroll
    for (int i = 0; i < 4; i++) {
        m[i] = -INFINITY; lsum[i] = 0.f;
        #pragma unroll
        for (int j = 0; j < 8; j++) o[i][j] = 0.f;
    }

    for (int kt = 0; kt <= qb; kt++) {
        const int k0 = kt << 6;
        for (int t = tid; t < 2048; t += 256) {
            int r = t >> 5, c4 = (t & 31) << 2;
            *(float4*)&KVs[r * 132 + c4] =
                *(const float4*)&proj[(tokbase + k0 + r) * PW + 2048 + coff + c4];
        }
        __syncthreads();

        float acc[4][4];
        #pragma unroll
        for (int i = 0; i < 4; i++)
            #pragma unroll
            for (int j = 0; j < 4; j++) acc[i][j] = 0.f;
        for (int kk = 0; kk < 128; kk += 4) {
            float4 qv[4], kv[4];
            #pragma unroll
            for (int i = 0; i < 4; i++) qv[i] = *(const float4*)&Qs[(ty4 + i) * 132 + kk];
            #pragma unroll
            for (int j = 0; j < 4; j++) kv[j] = *(const float4*)&KVs[(tx4 + j) * 132 + kk];
            #pragma unroll
            for (int i = 0; i < 4; i++)
                #pragma unroll
                for (int j = 0; j < 4; j++)
                    acc[i][j] += qv[i].x * kv[j].x + qv[i].y * kv[j].y
                               + qv[i].z * kv[j].z + qv[i].w * kv[j].w;
        }

        const bool diag = (kt == qb);
        #pragma unroll
        for (int i = 0; i < 4; i++) {
            int qg = q0 + ty4 + i;
            if (diag) {
                #pragma unroll
                for (int j = 0; j < 4; j++)
                    if (k0 + tx4 + j > qg) acc[i][j] = -INFINITY;
            }
            float mloc = fmaxf(fmaxf(acc[i][0], acc[i][1]), fmaxf(acc[i][2], acc[i][3]));
            #pragma unroll
            for (int off = 8; off; off >>= 1)
                mloc = fmaxf(mloc, __shfl_xor_sync(0xffffffffu, mloc, off));
            float mnew  = fmaxf(m[i], mloc);
            float alpha = expf(m[i] - mnew);
            float rs = 0.f;
            #pragma unroll
            for (int j = 0; j < 4; j++) {
                float p = expf(acc[i][j] - mnew);
                Ps[(ty4 + i) * 68 + tx4 + j] = p;
                rs += p;
            }
            #pragma unroll
            for (int off = 8; off; off >>= 1)
                rs += __shfl_xor_sync(0xffffffffu, rs, off);
            lsum[i] = lsum[i] * alpha + rs;
            m[i] = mnew;
            #pragma unroll
            for (int j = 0; j < 8; j++) o[i][j] *= alpha;
        }
        __syncthreads();

        for (int t = tid; t < 2048; t += 256) {
            int r = t >> 5, c4 = (t & 31) << 2;
            *(float4*)&KVs[r * 132 + c4] =
                *(const float4*)&proj[(tokbase + k0 + r) * PW + 4096 + coff + c4];
        }
        __syncthreads();

        for (int kk = 0; kk < 64; kk++) {
            float4 v0 = *(const float4*)&KVs[kk * 132 + tx8];
            float4 v1 = *(const float4*)&KVs[kk * 132 + tx8 + 4];
            #pragma unroll
            for (int i = 0; i < 4; i++) {
                float p = Ps[(ty4 + i) * 68 + kk];
                o[i][0] += p * v0.x; o[i][1] += p * v0.y;
                o[i][2] += p * v0.z; o[i][3] += p * v0.w;
                o[i][4] += p * v1.x; o[i][5] += p * v1.y;
                o[i][6] += p * v1.z; o[i][7] += p * v1.w;
            }
        }
        __syncthreads();
    }

    // epilogue: normalize, gate, split to bf16 hi/lo for GEMM2
    #pragma unroll
    for (int i = 0; i < 4; i++) {
        int qg = q0 + ty4 + i;
        size_t prow = (tokbase + qg) * PW;
        size_t arow = (tokbase + qg) * HIDN;
        float inv = 1.0f / lsum[i];
        #pragma unroll
        for (int j = 0; j < 8; j++) {
            int d = tx8 + j;
            float g = proj[prow + 6144 + coff + d];
            float v = o[i][j] * inv * g;
            __nv_bfloat16 hb = __float2bfloat16(v);
            att_hi[arow + coff + d] = hb;
            att_lo[arow + coff + d] = __float2bfloat16(v - __bfloat162float(hb));
        }
    }
}

// ---------------------------------------------------------------------------
extern "C" void kernel_launch(void* const* d_in, const int* in_sizes, int n_in,
                              void* d_out, int out_size)
{
    const float* hs    = (const float*)d_in[0];   // (4,2048,2048)
    const float* wqkvg = (const float*)d_in[1];   // (2048,8192)
    const float* wout  = (const float*)d_in[2];   // (2048,2048)
    float* out = (float*)d_out;

    float* proj;
    __nv_bfloat16 *hs_hi, *hs_lo, *wq_hi, *wq_lo, *wo_hi, *wo_lo, *at_hi, *at_lo;
    cudaGetSymbolAddress((void**)&proj,  g_proj);
    cudaGetSymbolAddress((void**)&hs_hi, g_hs_hi);
    cudaGetSymbolAddress((void**)&hs_lo, g_hs_lo);
    cudaGetSymbolAddress((void**)&wq_hi, g_wq_hi);
    cudaGetSymbolAddress((void**)&wq_lo, g_wq_lo);
    cudaGetSymbolAddress((void**)&wo_hi, g_wo_hi);
    cudaGetSymbolAddress((void**)&wo_lo, g_wo_lo);
    cudaGetSymbolAddress((void**)&at_hi, g_at_hi);
    cudaGetSymbolAddress((void**)&at_lo, g_at_lo);

    cudaFuncSetAttribute(gemm_bf16x3, cudaFuncAttributeMaxDynamicSharedMemorySize, GSM_TOTAL);
    cudaFuncSetAttribute(attn_kernel, cudaFuncAttributeMaxDynamicSharedMemorySize, ATT_SMEM);

    // 0) precision splits + weight transposes
    split_kernel<<<(TOK * HIDN / 4 + 255) / 256, 256>>>(hs, hs_hi, hs_lo, TOK * HIDN / 4);
    tsplit_kernel<<<dim3(PW / 32,   HIDN / 32), 256>>>(wqkvg, wq_hi, wq_lo, HIDN, PW);
    tsplit_kernel<<<dim3(HIDN / 32, HIDN / 32), 256>>>(wout,  wo_hi, wo_lo, HIDN, HIDN);

    // 1) QKVG projection (HMMA bf16x3)
    gemm_bf16x3<<<dim3(PW / 128, TOK / 128), 256, GSM_TOTAL>>>(
        hs_hi, hs_lo, wq_hi, wq_lo, proj, TOK, PW, HIDN);

    // 2) RMSNorm + RoPE + gate sigmoid, in place
    postproc<<<TOK, 128>>>(proj);

    // 3) causal flash attention, epilogue emits bf16 split
    attn_kernel<<<dim3(32, 64), 256, ATT_SMEM>>>(proj, at_hi, at_lo);

    // 4) output projection (HMMA bf16x3)
    gemm_bf16x3<<<dim3(HIDN / 128, TOK / 128), 256, GSM_TOTAL>>>(
        at_hi, at_lo, wo_hi, wo_lo, out, TOK, HIDN, HIDN);
}

// round 6
// speedup vs baseline: 5.9006x; 2.0499x over previous
#include <cuda_runtime.h>
#include <cuda_bf16.h>
#include <cstdint>
#include <math.h>

// Problem constants
#define TOK   8192      // B*L
#define HIDN  2048
#define PW    8192      // QKV (6144) + gate (2048)
#define LSEQ  2048

// ---------------------------------------------------------------------------
// Global scratch (allocation-free rule: device globals)
// ---------------------------------------------------------------------------
__device__ float          g_proj [(size_t)TOK * PW];    // 256 MB fp32
__device__ __nv_bfloat16  g_hs_hi[(size_t)TOK * HIDN];
__device__ __nv_bfloat16  g_hs_lo[(size_t)TOK * HIDN];
__device__ __nv_bfloat16  g_wq_hi[(size_t)PW  * HIDN];  // W_qkvg^T  [N][K]
__device__ __nv_bfloat16  g_wq_lo[(size_t)PW  * HIDN];
__device__ __nv_bfloat16  g_wo_hi[(size_t)HIDN* HIDN];  // W_out^T   [N][K]
__device__ __nv_bfloat16  g_wo_lo[(size_t)HIDN* HIDN];
__device__ __nv_bfloat16  g_at_hi[(size_t)TOK * HIDN];
__device__ __nv_bfloat16  g_at_lo[(size_t)TOK * HIDN];
// head-major attention operands [b,h,l,d] (q,k) and [b,h,d,l] (v transposed)
__device__ __nv_bfloat16  g_q_hi[(size_t)64 * LSEQ * 128];
__device__ __nv_bfloat16  g_q_lo[(size_t)64 * LSEQ * 128];
__device__ __nv_bfloat16  g_k_hi[(size_t)64 * LSEQ * 128];
__device__ __nv_bfloat16  g_k_lo[(size_t)64 * LSEQ * 128];
__device__ __nv_bfloat16  g_v_hi[(size_t)64 * 128 * LSEQ];
__device__ __nv_bfloat16  g_v_lo[(size_t)64 * 128 * LSEQ];

// ---------------------------------------------------------------------------
// Helpers
// ---------------------------------------------------------------------------
__device__ __forceinline__ uint32_t smem_to_u32(const void* smem_ptr) {
    uint32_t addr;
    asm("{ .reg .u64 tmp; cvta.to.shared.u64 tmp, %1; cvt.u32.u64 %0, tmp; }"
        : "=r"(addr) : "l"(smem_ptr));
    return addr;
}

#define SMEM_SWIZZLE_128B(byte_offset) \
    ((byte_offset) ^ ((((uint32_t)(byte_offset)) >> 3) & 0x70u))

#define CP_ASYNC_16(smem_u32, gptr) \
    asm volatile("cp.async.cg.shared.global [%0], [%1], 16;" \
                 :: "r"(smem_u32), "l"(gptr) : "memory")
#define CP_ASYNC_COMMIT() asm volatile("cp.async.commit_group;" ::: "memory")
#define CP_ASYNC_WAIT_1() asm volatile("cp.async.wait_group 1;" ::: "memory")
#define CP_ASYNC_WAIT_0() asm volatile("cp.async.wait_group 0;" ::: "memory")

#define LDSM_X4(r0, r1, r2, r3, addr) \
    asm volatile("ldmatrix.sync.aligned.m8n8.x4.shared.b16 {%0,%1,%2,%3}, [%4];" \
                 : "=r"(r0), "=r"(r1), "=r"(r2), "=r"(r3) : "r"(addr))

#define MMA_16816(c, a, b) \
    asm volatile("mma.sync.aligned.m16n8k16.row.col.f32.bf16.bf16.f32 " \
                 "{%0,%1,%2,%3}, {%4,%5,%6,%7}, {%8,%9}, {%0,%1,%2,%3};" \
                 : "+f"((c)[0]), "+f"((c)[1]), "+f"((c)[2]), "+f"((c)[3]) \
                 : "r"((a)[0]), "r"((a)[1]), "r"((a)[2]), "r"((a)[3]), \
                   "r"((b)[0]), "r"((b)[1]))

// pack two fp32 -> bf16x2 (lo = first arg, hi = second arg)
#define PACK_BF16X2(res, flo, fhi) \
    asm("cvt.rn.bf16x2.f32 %0, %1, %2;" : "=r"(res) : "f"(fhi), "f"(flo))

// ---------------------------------------------------------------------------
// elementwise fp32 -> bf16 hi/lo split
// ---------------------------------------------------------------------------
__global__ __launch_bounds__(256) void split_kernel(const float* __restrict__ x,
                                                    __nv_bfloat16* __restrict__ hi,
                                                    __nv_bfloat16* __restrict__ lo, int n4)
{
    int i = blockIdx.x * 256 + threadIdx.x;
    if (i >= n4) return;
    float4 v = ((const float4*)x)[i];
    float vv[4];
    vv[0] = v.x; vv[1] = v.y; vv[2] = v.z; vv[3] = v.w;
    __nv_bfloat16 hbuf[4], lbuf[4];
    #pragma unroll
    for (int j = 0; j < 4; j++) {
        __nv_bfloat16 h = __float2bfloat16(vv[j]);
        hbuf[j] = h;
        lbuf[j] = __float2bfloat16(vv[j] - __bfloat162float(h));
    }
    *(uint2*)&hi[(size_t)i * 4] = *(const uint2*)hbuf;
    *(uint2*)&lo[(size_t)i * 4] = *(const uint2*)lbuf;
}

// ---------------------------------------------------------------------------
// W [K][N] fp32  ->  Wt_hi/Wt_lo [N][K] bf16 (transpose + split)
// ---------------------------------------------------------------------------
__global__ __launch_bounds__(256) void tsplit_kernel(const float* __restrict__ W,
                                                     __nv_bfloat16* __restrict__ hi,
                                                     __nv_bfloat16* __restrict__ lo,
                                                     int K, int N)
{
    __shared__ float t[32][33];
    const int bn = blockIdx.x * 32;
    const int bk = blockIdx.y * 32;
    const int x = threadIdx.x & 31;
    const int y4 = (threadIdx.x >> 5) * 4;
    #pragma unroll
    for (int r = 0; r < 4; r++)
        t[y4 + r][x] = W[(size_t)(bk + y4 + r) * N + bn + x];
    __syncthreads();
    #pragma unroll
    for (int r = 0; r < 4; r++) {
        float v = t[x][y4 + r];
        __nv_bfloat16 h = __float2bfloat16(v);
        size_t o = (size_t)(bn + y4 + r) * K + bk + x;
        hi[o] = h;
        lo[o] = __float2bfloat16(v - __bfloat162float(h));
    }
}

// ---------------------------------------------------------------------------
// HMMA bf16x3 GEMM (unchanged from round 5 — proven correct/fast)
// ---------------------------------------------------------------------------
#define GSM_TILE  16384
#define GSM_BUF   (4 * GSM_TILE)
#define GSM_TOTAL (2 * GSM_BUF)

__global__ __launch_bounds__(256) void gemm_bf16x3(
    const __nv_bfloat16* __restrict__ Ahi, const __nv_bfloat16* __restrict__ Alo,
    const __nv_bfloat16* __restrict__ Bhi, const __nv_bfloat16* __restrict__ Blo,
    float* __restrict__ C, int M, int N, int K)
{
    extern __shared__ char smc[];
    const uint32_t sb = smem_to_u32(smc);
    const int tid  = threadIdx.x;
    const int wid  = tid >> 5;
    const int lane = tid & 31;
    const int wm   = wid & 1;
    const int wn   = wid >> 1;
    const int bm   = blockIdx.y << 7;
    const int bn   = blockIdx.x << 7;

    const int r0  = tid >> 3;
    const int c16 = tid & 7;

    const __nv_bfloat16* srcs[4];
    srcs[0] = Ahi + (size_t)bm * K;
    srcs[1] = Alo + (size_t)bm * K;
    srcs[2] = Bhi + (size_t)bn * K;
    srcs[3] = Blo + (size_t)bn * K;

    const int nc = K >> 6;

    auto issue_chunk = [&](int c, int buf) {
        const int k0 = c << 6;
        const uint32_t bufb = sb + buf * GSM_BUF;
        #pragma unroll
        for (int t = 0; t < 4; t++) {
            const __nv_bfloat16* s = srcs[t] + k0;
            #pragma unroll
            for (int rr = 0; rr < 4; rr++) {
                const int r = r0 + rr * 32;
                const uint32_t so = bufb + t * GSM_TILE +
                    SMEM_SWIZZLE_128B((uint32_t)(r * 128 + c16 * 16));
                CP_ASYNC_16(so, s + (size_t)r * K + c16 * 8);
            }
        }
    };

    float acc[4][4][4];
    #pragma unroll
    for (int mi = 0; mi < 4; mi++)
        #pragma unroll
        for (int ni = 0; ni < 4; ni++)
            #pragma unroll
            for (int j = 0; j < 4; j++) acc[mi][ni][j] = 0.f;

    const int lr   = lane & 7;
    const int a_row = lr + ((lane >> 3) & 1) * 8;
    const int a_kb  = ((lane >> 4) & 1) * 16;
    const int b_row = lr + ((lane >> 4) & 1) * 8;
    const int b_kb  = ((lane >> 3) & 1) * 16;

    issue_chunk(0, 0);
    CP_ASYNC_COMMIT();

    for (int c = 0; c < nc; c++) {
        const int buf = c & 1;
        if (c + 1 < nc) {
            issue_chunk(c + 1, buf ^ 1);
            CP_ASYNC_COMMIT();
            CP_ASYNC_WAIT_1();
        } else {
            CP_ASYNC_WAIT_0();
        }
        __syncthreads();

        const uint32_t Ab = sb + buf * GSM_BUF;
        const uint32_t Bb = Ab + 2 * GSM_TILE;

        #pragma unroll
        for (int ks = 0; ks < 4; ks++) {
            uint32_t ah[4][4], al[4][4], bh[4][2], bl[4][2];
            #pragma unroll
            for (int mi = 0; mi < 4; mi++) {
                const uint32_t off = SMEM_SWIZZLE_128B(
                    (uint32_t)((wm * 64 + mi * 16 + a_row) * 128 + ks * 32 + a_kb));
                LDSM_X4(ah[mi][0], ah[mi][1], ah[mi][2], ah[mi][3], Ab + off);
                LDSM_X4(al[mi][0], al[mi][1], al[mi][2], al[mi][3], Ab + GSM_TILE + off);
            }
            #pragma unroll
            for (int nb = 0; nb < 2; nb++) {
                const uint32_t off = SMEM_SWIZZLE_128B(
                    (uint32_t)((wn * 32 + nb * 16 + b_row) * 128 + ks * 32 + b_kb));
                uint32_t q0, q1, q2, q3;
                LDSM_X4(q0, q1, q2, q3, Bb + off);
                bh[nb * 2][0] = q0; bh[nb * 2][1] = q1;
                bh[nb * 2 + 1][0] = q2; bh[nb * 2 + 1][1] = q3;
                LDSM_X4(q0, q1, q2, q3, Bb + GSM_TILE + off);
                bl[nb * 2][0] = q0; bl[nb * 2][1] = q1;
                bl[nb * 2 + 1][0] = q2; bl[nb * 2 + 1][1] = q3;
            }
            #pragma unroll
            for (int mi = 0; mi < 4; mi++)
                #pragma unroll
                for (int ni = 0; ni < 4; ni++) {
                    MMA_16816(acc[mi][ni], ah[mi], bh[ni]);
                    MMA_16816(acc[mi][ni], ah[mi], bl[ni]);
                    MMA_16816(acc[mi][ni], al[mi], bh[ni]);
                }
        }
        __syncthreads();
    }

    const int g = lane >> 2, t2 = (lane & 3) * 2;
    #pragma unroll
    for (int mi = 0; mi < 4; mi++) {
        const int row0 = bm + wm * 64 + mi * 16 + g;
        #pragma unroll
        for (int ni = 0; ni < 4; ni++) {
            const int col = bn + wn * 32 + ni * 8 + t2;
            float2 v0; v0.x = acc[mi][ni][0]; v0.y = acc[mi][ni][1];
            float2 v1; v1.x = acc[mi][ni][2]; v1.y = acc[mi][ni][3];
            *(float2*)&C[(size_t)row0 * N + col]       = v0;
            *(float2*)&C[(size_t)(row0 + 8) * N + col] = v1;
        }
    }
}

// ---------------------------------------------------------------------------
// postproc: RMSNorm + RoPE, emits bf16 hi/lo q (pre-scaled 1/sqrt(DH)) and k
// in head-major [b,h,l,128]; sigmoid gate in place in proj.
// ---------------------------------------------------------------------------
__global__ __launch_bounds__(128) void postproc(
    float* __restrict__ proj,
    __nv_bfloat16* __restrict__ qhi, __nv_bfloat16* __restrict__ qlo,
    __nv_bfloat16* __restrict__ khi, __nv_bfloat16* __restrict__ klo)
{
    __shared__ float cosv[64], sinv[64], xbuf[128], red[4];
    const int row = blockIdx.x;
    const int bb  = row >> 11;
    const int l   = row & (LSEQ - 1);
    const int tid = threadIdx.x;

    if (tid < 64) {
        double f   = pow(10000.0, -(double)tid / 64.0);
        double ang = (double)l * f;
        double s, c;
        sincos(ang, &s, &c);
        cosv[tid] = (float)c;
        sinv[tid] = (float)s;
    }
    __syncthreads();

    const size_t base0 = (size_t)row * PW;
    for (int hh = 0; hh < 32; hh++) {
        const size_t base = base0 + hh * 128;
        float x = proj[base + tid];
        float v = x * x;
        #pragma unroll
        for (int o = 16; o; o >>= 1) v += __shfl_xor_sync(0xffffffffu, v, o);
        if ((tid & 31) == 0) red[tid >> 5] = v;
        __syncthreads();
        float total = red[0] + red[1] + red[2] + red[3];
        float scale = 1.0f / sqrtf(total * 0.0078125f + 1e-5f);
        xbuf[tid] = x * scale;
        __syncthreads();
        if (tid < 64) {
            float x1 = xbuf[tid], x2 = xbuf[tid + 64];
            float c = cosv[tid], s = sinv[tid];
            float y1 = x1 * c - x2 * s;
            float y2 = x1 * s + x2 * c;
            const int hd = hh & 15;
            const float sc = (hh < 16) ? 0.08838834764831845f : 1.0f;
            y1 *= sc; y2 *= sc;
            __nv_bfloat16* dh = (hh < 16) ? qhi : khi;
            __nv_bfloat16* dl = (hh < 16) ? qlo : klo;
            const size_t ob = ((size_t)(bb * 16 + hd) * LSEQ + l) * 128;
            __nv_bfloat16 h1 = __float2bfloat16(y1);
            __nv_bfloat16 h2 = __float2bfloat16(y2);
            dh[ob + tid]      = h1;
            dh[ob + tid + 64] = h2;
            dl[ob + tid]      = __float2bfloat16(y1 - __bfloat162float(h1));
            dl[ob + tid + 64] = __float2bfloat16(y2 - __bfloat162float(h2));
        }
        __syncthreads();
    }
    for (int it = 0; it < 16; it++) {
        size_t idx = base0 + 6144 + it * 128 + tid;
        float g = proj[idx];
        proj[idx] = 1.0f / (1.0f + expf(-g));
    }
}

// ---------------------------------------------------------------------------
// vsplit: V slice of proj [b,l,h,d] fp32 -> transposed bf16 hi/lo [b,h,d,l]
// ---------------------------------------------------------------------------
__global__ __launch_bounds__(256) void vsplit(const float* __restrict__ proj,
                                              __nv_bfloat16* __restrict__ vhit,
                                              __nv_bfloat16* __restrict__ vlot)
{
    __shared__ float t[32][33];
    const int l0 = blockIdx.x * 32;
    const int d0 = blockIdx.y * 32;
    const int bh = blockIdx.z;
    const int b = bh >> 4, h = bh & 15;
    const int x = threadIdx.x & 31, y = threadIdx.x >> 5;
    #pragma unroll
    for (int i = 0; i < 4; i++) {
        int ll = y + i * 8;
        t[ll][x] = proj[((size_t)b * LSEQ + l0 + ll) * PW + 4096 + h * 128 + d0 + x];
    }
    __syncthreads();
    #pragma unroll
    for (int i = 0; i < 4; i++) {
        int d = y + i * 8;
        float v = t[x][d];
        size_t o = ((size_t)bh * 128 + d0 + d) * LSEQ + l0 + x;
        __nv_bfloat16 hb = __float2bfloat16(v);
        vhit[o] = hb;
        vlot[o] = __float2bfloat16(v - __bfloat162float(hb));
    }
}

// ---------------------------------------------------------------------------
// HMMA bf16x3 causal flash attention. BM=64, BN=64, 4 warps (16 q-rows each).
// smem: QH0/QH1/QL0/QL1/KH0/KH1/KL0/KL1 [64][64] + VH/VL [128][64] = 96 KB.
// ---------------------------------------------------------------------------
#define ASM_QH 0
#define ASM_QL 16384
#define ASM_KH 32768
#define ASM_KL 49152
#define ASM_VH 65536
#define ASM_VL 81920
#define ATTN_SMEM 98304

__global__ __launch_bounds__(128) void attn_hmma(
    const __nv_bfloat16* __restrict__ qhi, const __nv_bfloat16* __restrict__ qlo,
    const __nv_bfloat16* __restrict__ khi, const __nv_bfloat16* __restrict__ klo,
    const __nv_bfloat16* __restrict__ vhit, const __nv_bfloat16* __restrict__ vlot,
    const float* __restrict__ proj,
    __nv_bfloat16* __restrict__ att_hi, __nv_bfloat16* __restrict__ att_lo)
{
    extern __shared__ char smc[];
    const uint32_t sb = smem_to_u32(smc);
    const int tid = threadIdx.x, wid = tid >> 5, lane = tid & 31;
    const int qb = (int)gridDim.x - 1 - (int)blockIdx.x;   // heavy blocks first
    const int bh = blockIdx.y;
    const int b = bh >> 4, h = bh & 15;
    const int q0 = qb << 6;
    const size_t hbase = (size_t)bh * LSEQ * 128;
    const size_t vbase = (size_t)bh * 128 * LSEQ;
    const size_t tokbase = (size_t)b * LSEQ;

    const int r0 = tid >> 3;      // 0..15
    const int c16 = tid & 7;

    const int lr = lane & 7;
    const int a_row = lr + ((lane >> 3) & 1) * 8;
    const int a_kb  = ((lane >> 4) & 1) * 16;
    const int b_row = lr + ((lane >> 4) & 1) * 8;
    const int b_kb  = ((lane >> 3) & 1) * 16;
    const int g  = lane >> 2;
    const int t2 = (lane & 3) * 2;

    // ---- load Q tiles (persistent) ----
    #pragma unroll
    for (int i = 0; i < 4; i++) {
        const int r = r0 + i * 16;
        const uint32_t so = SMEM_SWIZZLE_128B((uint32_t)(r * 128 + c16 * 16));
        const size_t gq = hbase + (size_t)(q0 + r) * 128 + c16 * 8;
        CP_ASYNC_16(sb + ASM_QH        + so, qhi + gq);
        CP_ASYNC_16(sb + ASM_QH + 8192 + so, qhi + gq + 64);
        CP_ASYNC_16(sb + ASM_QL        + so, qlo + gq);
        CP_ASYNC_16(sb + ASM_QL + 8192 + so, qlo + gq + 64);
    }
    CP_ASYNC_COMMIT();

    float o[16][4];
    #pragma unroll
    for (int nt = 0; nt < 16; nt++)
        #pragma unroll
        for (int j = 0; j < 4; j++) o[nt][j] = 0.f;
    float m0 = -1e30f, m1 = -1e30f, lsum0 = 0.f, lsum1 = 0.f;

    for (int kt = 0; kt <= qb; kt++) {
        const int k0 = kt << 6;
        // ---- load K tiles ----
        #pragma unroll
        for (int i = 0; i < 4; i++) {
            const int r = r0 + i * 16;
            const uint32_t so = SMEM_SWIZZLE_128B((uint32_t)(r * 128 + c16 * 16));
            const size_t gk = hbase + (size_t)(k0 + r) * 128 + c16 * 8;
            CP_ASYNC_16(sb + ASM_KH        + so, khi + gk);
            CP_ASYNC_16(sb + ASM_KH + 8192 + so, khi + gk + 64);
            CP_ASYNC_16(sb + ASM_KL        + so, klo + gk);
            CP_ASYNC_16(sb + ASM_KL + 8192 + so, klo + gk + 64);
        }
        // ---- load V^T tiles ----
        #pragma unroll
        for (int i = 0; i < 8; i++) {
            const int d = r0 + i * 16;
            const uint32_t so = SMEM_SWIZZLE_128B((uint32_t)(d * 128 + c16 * 16));
            const size_t gv = vbase + (size_t)d * LSEQ + k0 + c16 * 8;
            CP_ASYNC_16(sb + ASM_VH + so, vhit + gv);
            CP_ASYNC_16(sb + ASM_VL + so, vlot + gv);
        }
        CP_ASYNC_COMMIT();
        CP_ASYNC_WAIT_0();
        __syncthreads();

        // ---- S = Q K^T (3-pass bf16x3) ----
        float s[8][4];
        #pragma unroll
        for (int nb = 0; nb < 8; nb++)
            #pragma unroll
            for (int j = 0; j < 4; j++) s[nb][j] = 0.f;

        #pragma unroll
        for (int ks = 0; ks < 8; ks++) {
            const uint32_t qt = sb + ASM_QH + (ks >> 2) * 8192;
            const uint32_t kt_ = sb + ASM_KH + (ks >> 2) * 8192;
            const uint32_t kb = (ks & 3) * 32;
            uint32_t ah[4], al[4];
            const uint32_t aoff = SMEM_SWIZZLE_128B(
                (uint32_t)((wid * 16 + a_row) * 128 + kb + a_kb));
            LDSM_X4(ah[0], ah[1], ah[2], ah[3], qt + aoff);
            LDSM_X4(al[0], al[1], al[2], al[3], qt + 16384 + aoff);
            #pragma unroll
            for (int ng = 0; ng < 4; ng++) {
                const uint32_t boff = SMEM_SWIZZLE_128B(
                    (uint32_t)((ng * 16 + b_row) * 128 + kb + b_kb));
                uint32_t h0, h1, h2, h3, l0_, l1_, l2_, l3_;
                LDSM_X4(h0, h1, h2, h3, kt_ + boff);
                LDSM_X4(l0_, l1_, l2_, l3_, kt_ + 16384 + boff);
                uint32_t bh0[2] = {h0, h1}, bh1[2] = {h2, h3};
                uint32_t bl0[2] = {l0_, l1_}, bl1[2] = {l2_, l3_};
                MMA_16816(s[ng * 2],     ah, bh0);
                MMA_16816(s[ng * 2 + 1], ah, bh1);
                MMA_16816(s[ng * 2],     ah, bl0);
                MMA_16816(s[ng * 2 + 1], ah, bl1);
                MMA_16816(s[ng * 2],     al, bh0);
                MMA_16816(s[ng * 2 + 1], al, bh1);
            }
        }

        // ---- causal mask (diag tile only) ----
        if (kt == qb) {
            const int qr = wid * 16 + g;
            #pragma unroll
            for (int nb = 0; nb < 8; nb++) {
                const int col = nb * 8 + t2;
                if (col     > qr)     s[nb][0] = -1e30f;
                if (col + 1 > qr)     s[nb][1] = -1e30f;
                if (col     > qr + 8) s[nb][2] = -1e30f;
                if (col + 1 > qr + 8) s[nb][3] = -1e30f;
            }
        }

        // ---- online softmax (two rows per thread: g and g+8) ----
        float mx0 = -1e30f, mx1 = -1e30f;
        #pragma unroll
        for (int nb = 0; nb < 8; nb++) {
            mx0 = fmaxf(mx0, fmaxf(s[nb][0], s[nb][1]));
            mx1 = fmaxf(mx1, fmaxf(s[nb][2], s[nb][3]));
        }
        mx0 = fmaxf(mx0, __shfl_xor_sync(0xffffffffu, mx0, 1));
        mx0 = fmaxf(mx0, __shfl_xor_sync(0xffffffffu, mx0, 2));
        mx1 = fmaxf(mx1, __shfl_xor_sync(0xffffffffu, mx1, 1));
        mx1 = fmaxf(mx1, __shfl_xor_sync(0xffffffffu, mx1, 2));
        const float mn0 = fmaxf(m0, mx0), mn1 = fmaxf(m1, mx1);
        const float al0 = __expf(m0 - mn0), al1 = __expf(m1 - mn1);
        m0 = mn0; m1 = mn1;

        float rs0 = 0.f, rs1 = 0.f;
        uint32_t pHg[8], pHg8[8], pLg[8], pLg8[8];
        #pragma unroll
        for (int nb = 0; nb < 8; nb++) {
            float p0 = __expf(s[nb][0] - mn0), p1 = __expf(s[nb][1] - mn0);
            float p2 = __expf(s[nb][2] - mn1), p3 = __expf(s[nb][3] - mn1);
            rs0 += p0 + p1; rs1 += p2 + p3;
            uint32_t hg, hg8;
            PACK_BF16X2(hg,  p0, p1);
            PACK_BF16X2(hg8, p2, p3);
            pHg[nb] = hg; pHg8[nb] = hg8;
            float h0 = __uint_as_float(hg << 16);
            float h1 = __uint_as_float(hg & 0xFFFF0000u);
            float h2 = __uint_as_float(hg8 << 16);
            float h3 = __uint_as_float(hg8 & 0xFFFF0000u);
            uint32_t lg, lg8;
            PACK_BF16X2(lg,  p0 - h0, p1 - h1);
            PACK_BF16X2(lg8, p2 - h2, p3 - h3);
            pLg[nb] = lg; pLg8[nb] = lg8;
        }
        rs0 += __shfl_xor_sync(0xffffffffu, rs0, 1);
        rs0 += __shfl_xor_sync(0xffffffffu, rs0, 2);
        rs1 += __shfl_xor_sync(0xffffffffu, rs1, 1);
        rs1 += __shfl_xor_sync(0xffffffffu, rs1, 2);
        lsum0 = lsum0 * al0 + rs0;
        lsum1 = lsum1 * al1 + rs1;
        #pragma unroll
        for (int nt = 0; nt < 16; nt++) {
            o[nt][0] *= al0; o[nt][1] *= al0;
            o[nt][2] *= al1; o[nt][3] *= al1;
        }

        // ---- O += P V (3-pass) ----
        #pragma unroll
        for (int kn = 0; kn < 4; kn++) {
            uint32_t aH[4] = {pHg[2 * kn], pHg8[2 * kn], pHg[2 * kn + 1], pHg8[2 * kn + 1]};
            uint32_t aL[4] = {pLg[2 * kn], pLg8[2 * kn], pLg[2 * kn + 1], pLg8[2 * kn + 1]};
            #pragma unroll
            for (int ng = 0; ng < 8; ng++) {
                const uint32_t boff = SMEM_SWIZZLE_128B(
                    (uint32_t)((ng * 16 + b_row) * 128 + kn * 32 + b_kb));
                uint32_t h0, h1, h2, h3, l0_, l1_, l2_, l3_;
                LDSM_X4(h0, h1, h2, h3, sb + ASM_VH + boff);
                LDSM_X4(l0_, l1_, l2_, l3_, sb + ASM_VL + boff);
                uint32_t vh0[2] = {h0, h1}, vh1[2] = {h2, h3};
                uint32_t vl0[2] = {l0_, l1_}, vl1[2] = {l2_, l3_};
                MMA_16816(o[ng * 2],     aH, vh0);
                MMA_16816(o[ng * 2 + 1], aH, vh1);
                MMA_16816(o[ng * 2],     aH, vl0);
                MMA_16816(o[ng * 2 + 1], aH, vl1);
                MMA_16816(o[ng * 2],     aL, vh0);
                MMA_16816(o[ng * 2 + 1], aL, vh1);
            }
        }
        __syncthreads();
    }

    // ---- epilogue: normalize, gate, split to bf16 hi/lo (packed stores) ----
    const float inv0 = 1.0f / lsum0;
    const float inv1 = 1.0f / lsum1;
    const int qr0 = q0 + wid * 16 + g;
    const int qr1 = qr0 + 8;
    const size_t prow0 = (tokbase + qr0) * PW + 6144 + h * 128;
    const size_t prow1 = (tokbase + qr1) * PW + 6144 + h * 128;
    const size_t arow0 = (tokbase + qr0) * HIDN + h * 128;
    const size_t arow1 = (tokbase + qr1) * HIDN + h * 128;
    #pragma unroll
    for (int nb = 0; nb < 16; nb++) {
        const int d = nb * 8 + t2;
        float2 g0 = *(const float2*)&proj[prow0 + d];
        float2 g1 = *(const float2*)&proj[prow1 + d];
        float x0 = o[nb][0] * inv0 * g0.x;
        float x1 = o[nb][1] * inv0 * g0.y;
        float x2 = o[nb][2] * inv1 * g1.x;
        float x3 = o[nb][3] * inv1 * g1.y;
        uint32_t hp0, hp1;
        PACK_BF16X2(hp0, x0, x1);
        PACK_BF16X2(hp1, x2, x3);
        float h0 = __uint_as_float(hp0 << 16);
        float h1 = __uint_as_float(hp0 & 0xFFFF0000u);
        float h2 = __uint_as_float(hp1 << 16);
        float h3 = __uint_as_float(hp1 & 0xFFFF0000u);
        uint32_t lp0, lp1;
        PACK_BF16X2(lp0, x0 - h0, x1 - h1);
        PACK_BF16X2(lp1, x2 - h2, x3 - h3);
        *(uint32_t*)&att_hi[arow0 + d] = hp0;
        *(uint32_t*)&att_lo[arow0 + d] = lp0;
        *(uint32_t*)&att_hi[arow1 + d] = hp1;
        *(uint32_t*)&att_lo[arow1 + d] = lp1;
    }
}

// ---------------------------------------------------------------------------
extern "C" void kernel_launch(void* const* d_in, const int* in_sizes, int n_in,
                              void* d_out, int out_size)
{
    const float* hs    = (const float*)d_in[0];   // (4,2048,2048)
    const float* wqkvg = (const float*)d_in[1];   // (2048,8192)
    const float* wout  = (const float*)d_in[2];   // (2048,2048)
    float* out = (float*)d_out;

    float* proj;
    __nv_bfloat16 *hs_hi, *hs_lo, *wq_hi, *wq_lo, *wo_hi, *wo_lo, *at_hi, *at_lo;
    __nv_bfloat16 *q_hi, *q_lo, *k_hi, *k_lo, *v_hi, *v_lo;
    cudaGetSymbolAddress((void**)&proj,  g_proj);
    cudaGetSymbolAddress((void**)&hs_hi, g_hs_hi);
    cudaGetSymbolAddress((void**)&hs_lo, g_hs_lo);
    cudaGetSymbolAddress((void**)&wq_hi, g_wq_hi);
    cudaGetSymbolAddress((void**)&wq_lo, g_wq_lo);
    cudaGetSymbolAddress((void**)&wo_hi, g_wo_hi);
    cudaGetSymbolAddress((void**)&wo_lo, g_wo_lo);
    cudaGetSymbolAddress((void**)&at_hi, g_at_hi);
    cudaGetSymbolAddress((void**)&at_lo, g_at_lo);
    cudaGetSymbolAddress((void**)&q_hi,  g_q_hi);
    cudaGetSymbolAddress((void**)&q_lo,  g_q_lo);
    cudaGetSymbolAddress((void**)&k_hi,  g_k_hi);
    cudaGetSymbolAddress((void**)&k_lo,  g_k_lo);
    cudaGetSymbolAddress((void**)&v_hi,  g_v_hi);
    cudaGetSymbolAddress((void**)&v_lo,  g_v_lo);

    cudaFuncSetAttribute(gemm_bf16x3, cudaFuncAttributeMaxDynamicSharedMemorySize, GSM_TOTAL);
    cudaFuncSetAttribute(attn_hmma,   cudaFuncAttributeMaxDynamicSharedMemorySize, ATTN_SMEM);

    // 0) precision splits + weight transposes
    split_kernel<<<(TOK * HIDN / 4 + 255) / 256, 256>>>(hs, hs_hi, hs_lo, TOK * HIDN / 4);
    tsplit_kernel<<<dim3(PW / 32,   HIDN / 32), 256>>>(wqkvg, wq_hi, wq_lo, HIDN, PW);
    tsplit_kernel<<<dim3(HIDN / 32, HIDN / 32), 256>>>(wout,  wo_hi, wo_lo, HIDN, HIDN);

    // 1) QKVG projection (HMMA bf16x3)
    gemm_bf16x3<<<dim3(PW / 128, TOK / 128), 256, GSM_TOTAL>>>(
        hs_hi, hs_lo, wq_hi, wq_lo, proj, TOK, PW, HIDN);

    // 2) RMSNorm + RoPE -> bf16 splits; gate sigmoid in place
    postproc<<<TOK, 128>>>(proj, q_hi, q_lo, k_hi, k_lo);

    // 2b) V transpose + split
    vsplit<<<dim3(LSEQ / 32, 4, 64), 256>>>(proj, v_hi, v_lo);

    // 3) HMMA causal flash attention (gate fused, emits bf16 split)
    attn_hmma<<<dim3(32, 64), 128, ATTN_SMEM>>>(
        q_hi, q_lo, k_hi, k_lo, v_hi, v_lo, proj, at_hi, at_lo);

    // 4) output projection (HMMA bf16x3)
    gemm_bf16x3<<<dim3(HIDN / 128, TOK / 128), 256, GSM_TOTAL>>>(
        at_hi, at_lo, wo_hi, wo_lo, out, TOK, HIDN, HIDN);
}